// round 8
// baseline (speedup 1.0000x reference)
#include <cuda_runtime.h>
#include <cuda_bf16.h>
#include <cstdint>

// RankedListLoss, round 7 (resubmit of r5 design): mma.sync bf16 + ldmatrix,
// upper-triangular 128x128 tiles, fused epilogue, last-block finalize.
//
// dist(i,j) = sq_i + sq_j - 2*dot(e_i,e_j)   (sq fp32, dot bf16 tensor cores)
// pos: sum {same class, i!=j, dist > 0.8} (dist - 0.8)
// neg: per class, softmax-weighted gap over cross-class pairs with dist < 1.2

#define NMAX 8192
#define DIM 128
#define BM 128
#define LDT 136            /* padded smem row stride (bf16 elems) */
#define APM 0.8f
#define ALPHAC 1.2f
#define TC 10.0f

__device__ float          d_sq[NMAX];
__device__ int            d_lab[NMAX];
__device__ __nv_bfloat16  d_ebf[NMAX * DIM];
__device__ double         d_pos;
__device__ float          d_cw[64];
__device__ float          d_cn[64];
__device__ int            d_done;

// ---------------------------------------------------------------------------
// Prep: dtype-detect labels, zero accumulators (block 0), norms + bf16 copy.
__global__ void k_prep(const float* __restrict__ emb, const void* labraw, int n) {
    __shared__ int s_mode;
    if (threadIdx.x == 0) {
        const int* lr = (const int*)labraw;
        int allz = 1;
        int lim = (n < 32 ? n : 32);
        for (int i = 0; i < lim; i++) allz &= (lr[2 * i + 1] == 0);
        s_mode = allz;                  // all odd int32 slots zero => int64 labels
    }
    if (blockIdx.x == 0) {
        if (threadIdx.x < 64) { d_cw[threadIdx.x] = 0.0f; d_cn[threadIdx.x] = 0.0f; }
        if (threadIdx.x == 0) { d_pos = 0.0; d_done = 0; }
    }
    __syncthreads();
    int i = blockIdx.x * blockDim.x + threadIdx.x;
    if (i >= n) return;
    d_lab[i] = s_mode ? ((const int2*)labraw)[i].x : ((const int*)labraw)[i];
    const float4* r = (const float4*)(emb + (size_t)i * DIM);
    __nv_bfloat16* eb = d_ebf + (size_t)i * DIM;
    float s = 0.0f;
    #pragma unroll
    for (int q = 0; q < DIM / 4; q++) {
        float4 v = r[q];
        s += v.x * v.x + v.y * v.y + v.z * v.z + v.w * v.w;
        eb[q * 4 + 0] = __float2bfloat16(v.x);
        eb[q * 4 + 1] = __float2bfloat16(v.y);
        eb[q * 4 + 2] = __float2bfloat16(v.z);
        eb[q * 4 + 3] = __float2bfloat16(v.w);
    }
    d_sq[i] = s;
}

// ---------------------------------------------------------------------------
__device__ __forceinline__ void mma_bf16(float* d, const uint32_t* a, const uint32_t* b) {
    asm volatile(
        "mma.sync.aligned.m16n8k16.row.col.f32.bf16.bf16.f32 "
        "{%0,%1,%2,%3}, {%4,%5,%6,%7}, {%8,%9}, {%0,%1,%2,%3};"
        : "+f"(d[0]), "+f"(d[1]), "+f"(d[2]), "+f"(d[3])
        : "r"(a[0]), "r"(a[1]), "r"(a[2]), "r"(a[3]), "r"(b[0]), "r"(b[1]));
}
__device__ __forceinline__ void ldmx4(uint32_t* r, uint32_t addr) {
    asm volatile("ldmatrix.sync.aligned.m8n8.x4.shared.b16 {%0,%1,%2,%3}, [%4];"
        : "=r"(r[0]), "=r"(r[1]), "=r"(r[2]), "=r"(r[3]) : "r"(addr));
}
__device__ __forceinline__ uint32_t smem_u32(const void* p) {
    uint32_t a;
    asm("{ .reg .u64 t; cvta.to.shared.u64 t, %1; cvt.u32.u64 %0, t; }" : "=r"(a) : "l"(p));
    return a;
}

// smem layout (dynamic)
#define SM_RED 0                   /* 256 floats */
#define SM_SQI 1024
#define SM_SQJ 1536
#define SM_LI  2048
#define SM_LJ  2560
#define SM_A   3072                /* 128 x LDT bf16 = 34816 B */
#define SM_B   (SM_A + BM * LDT * 2)
#define SM_TOTAL (SM_B + BM * LDT * 2)

__global__ __launch_bounds__(256, 2) void k_main(int n, float* out, int out_size) {
    extern __shared__ char smem[];
    __nv_bfloat16* As = (__nv_bfloat16*)(smem + SM_A);
    __nv_bfloat16* Bs = (__nv_bfloat16*)(smem + SM_B);
    float* sqi_s = (float*)(smem + SM_SQI);
    float* sqj_s = (float*)(smem + SM_SQJ);
    int*   li_s  = (int*)(smem + SM_LI);
    int*   lj_s  = (int*)(smem + SM_LJ);

    const int t = threadIdx.x, w = t >> 5, lane = t & 31;
    const int warp_m = w & 1;          // 2 row groups of 64
    const int warp_n = w >> 1;         // 4 col groups of 32

    // triangular decode: bid -> (ti, tj), ti <= tj
    const int NT = n / BM;
    int bid = blockIdx.x;
    float fN = (float)NT;
    float disc = (2.0f * fN + 1.0f) * (2.0f * fN + 1.0f) - 8.0f * (float)bid;
    int ti = (int)(((2.0f * fN + 1.0f) - sqrtf(disc)) * 0.5f);
    while (ti > 0 && bid < ti * NT - (ti * (ti - 1)) / 2) ti--;
    while (bid >= (ti + 1) * NT - ((ti + 1) * ti) / 2) ti++;
    int tj = ti + (bid - (ti * NT - (ti * (ti - 1)) / 2));
    const int rowBase = ti * BM, colBase = tj * BM;

    // ---- load whole-K tiles into padded smem (+ stage sq/lab) ----
    {
        const uint4* gA = (const uint4*)(d_ebf + (size_t)rowBase * DIM);
        const uint4* gB = (const uint4*)(d_ebf + (size_t)colBase * DIM);
        #pragma unroll
        for (int i = 0; i < 8; i++) {
            int idx = t + i * 256;                 // 0..2047
            int row = idx >> 4, c8 = idx & 15;
            uint4 va = gA[row * 16 + c8];
            uint4 vb = gB[row * 16 + c8];
            *(uint4*)(As + row * LDT + c8 * 8) = va;
            *(uint4*)(Bs + row * LDT + c8 * 8) = vb;
        }
        if (t < 128) {
            sqi_s[t] = d_sq[rowBase + t];  li_s[t] = d_lab[rowBase + t];
            sqj_s[t] = d_sq[colBase + t];  lj_s[t] = d_lab[colBase + t];
        }
    }
    __syncthreads();

    // ---- MMA: warp tile 64x32, m16n8k16, 8 K-steps, ldmatrix loads ----
    float acc[4][4][4];
    #pragma unroll
    for (int mt = 0; mt < 4; mt++)
        #pragma unroll
        for (int nt = 0; nt < 4; nt++)
            #pragma unroll
            for (int q = 0; q < 4; q++) acc[mt][nt][q] = 0.0f;

    // per-lane ldmatrix base addresses
    const uint32_t sbA = smem_u32(As), sbB = smem_u32(Bs);
    // A x4: lanes 0-15 -> rows 0-15 @k, lanes 16-31 -> rows 0-15 @k+8
    const int rowA  = (lane & 15);
    const int kparA = (lane >> 4) * 8;
    uint32_t adA[4];
    #pragma unroll
    for (int mt = 0; mt < 4; mt++)
        adA[mt] = sbA + ((warp_m * 64 + mt * 16 + rowA) * LDT + kparA) * 2;
    // B x4: groups (n0-7,k) (n0-7,k+8) (n8-15,k) (n8-15,k+8)
    const int rowB  = ((lane >> 4) * 8) + (lane & 7);
    const int kparB = ((lane >> 3) & 1) * 8;
    uint32_t adB[2];
    #pragma unroll
    for (int p = 0; p < 2; p++)
        adB[p] = sbB + ((warp_n * 32 + p * 16 + rowB) * LDT + kparB) * 2;

    #pragma unroll
    for (int ks = 0; ks < 8; ks++) {
        uint32_t a[4][4], b[2][4];
        #pragma unroll
        for (int mt = 0; mt < 4; mt++) { ldmx4(a[mt], adA[mt]); adA[mt] += 32; }
        #pragma unroll
        for (int p = 0; p < 2; p++)    { ldmx4(b[p],  adB[p]);  adB[p]  += 32; }
        #pragma unroll
        for (int mt = 0; mt < 4; mt++) {
            mma_bf16(acc[mt][0], a[mt], &b[0][0]);
            mma_bf16(acc[mt][1], a[mt], &b[0][2]);
            mma_bf16(acc[mt][2], a[mt], &b[1][0]);
            mma_bf16(acc[mt][3], a[mt], &b[1][2]);
        }
    }

    // ---- fused epilogue ----
    // preload row/col metadata into registers
    float rsq[8], csq[8];
    int   rlb[8], clb[8];
    #pragma unroll
    for (int u = 0; u < 8; u++) {
        int il = warp_m * 64 + (u >> 1) * 16 + (lane >> 2) + (u & 1) * 8;
        rsq[u] = sqi_s[il]; rlb[u] = li_s[il];
        int jl = warp_n * 32 + (u >> 1) * 8 + (lane & 3) * 2 + (u & 1);
        csq[u] = sqj_s[jl]; clb[u] = lj_s[jl];
    }

    const bool diag = (ti == tj);
    float pos0 = 0.0f, pos1 = 0.0f;

    #pragma unroll
    for (int mt = 0; mt < 4; mt++) {
        #pragma unroll
        for (int nt = 0; nt < 4; nt++) {
            #pragma unroll
            for (int q = 0; q < 4; q++) {
                int ui = mt * 2 + (q >> 1);
                int uj = nt * 2 + (q & 1);
                if (diag) {
                    int gi = rowBase + warp_m * 64 + mt * 16 + (lane >> 2) + (q >> 1) * 8;
                    int gj = colBase + warp_n * 32 + nt * 8 + (lane & 3) * 2 + (q & 1);
                    if (gj <= gi) continue;
                }
                float dist = fmaf(-2.0f, acc[mt][nt][q], rsq[ui] + csq[uj]);
                int li = rlb[ui], lj = clb[uj];
                if (li == lj) {
                    if (dist > APM) { if (q & 1) pos1 += dist - APM; else pos0 += dist - APM; }
                } else if (dist < ALPHAC) {          // statistically cold
                    float gap = ALPHAC - dist;
                    float ww = expf(TC * gap);
                    atomicAdd(&d_cw[li], ww); atomicAdd(&d_cn[li], gap * ww);
                    atomicAdd(&d_cw[lj], ww); atomicAdd(&d_cn[lj], gap * ww);
                }
            }
        }
    }
    float pos = (pos0 + pos1) * 2.0f;   // each unordered pair appears twice

    // block reduce -> one double atomic
    float* red = (float*)(smem + SM_RED);
    red[t] = pos;
    __syncthreads();
    for (int s = 128; s > 0; s >>= 1) {
        if (t < s) red[t] += red[t + s];
        __syncthreads();
    }
    if (t == 0) {
        atomicAdd(&d_pos, (double)red[0]);
        __threadfence();
        int ticket = atomicAdd(&d_done, 1);
        if (ticket == (int)gridDim.x - 1) {
            __threadfence();
            // last block: finalize (volatile reads bypass stale caching)
            volatile float* vw = d_cw;
            volatile float* vn = d_cn;
            volatile double* vp = &d_pos;
            double neg = 0.0;
            #pragma unroll 8
            for (int c = 0; c < 64; c++) {
                float wv = vw[c];
                if (wv > 0.0f) neg += (double)(vn[c] / wv);
            }
            out[0] = (float)(*vp + neg);
            if (out_size > 1) out[1] = (float)n;
        }
    }
}

// ---------------------------------------------------------------------------
extern "C" void kernel_launch(void* const* d_in, const int* in_sizes, int n_in,
                              void* d_out, int out_size) {
    const float* emb = (const float*)d_in[0];
    const void*  lab = d_in[1];
    int n = in_sizes[1];               // 8192
    float* out = (float*)d_out;

    cudaFuncSetAttribute(k_main, cudaFuncAttributeMaxDynamicSharedMemorySize, SM_TOTAL);

    k_prep<<<(n + 255) / 256, 256>>>(emb, lab, n);

    int nt = n / BM;
    int nblocks = nt * (nt + 1) / 2;
    k_main<<<nblocks, 256, SM_TOTAL>>>(n, out, out_size);
}

// round 11
// speedup vs baseline: 1.4727x; 1.4727x over previous
#include <cuda_runtime.h>
#include <cuda_bf16.h>
#include <cstdint>

// RankedListLoss, round 9: parallel prep (warp/row), mma.sync bf16 + ldmatrix,
// cp.async tile loads, shuffle block-reduce, last-block finalize.
//
// dist(i,j) = sq_i + sq_j - 2*dot(e_i,e_j)   (sq fp32, dot bf16 tensor cores)
// pos: sum {same class, i!=j, dist > 0.8} (dist - 0.8)
// neg: per class, softmax-weighted gap over cross-class pairs with dist < 1.2

#define NMAX 8192
#define DIM 128
#define BM 128
#define LDT 136            /* padded smem row stride (bf16 elems); 272B = 17*16 */
#define APM 0.8f
#define ALPHAC 1.2f
#define TC 10.0f

__device__ float          d_sq[NMAX];
__device__ int            d_lab[NMAX];
__device__ __nv_bfloat16  d_ebf[NMAX * DIM];
__device__ double         d_pos;
__device__ float          d_cw[64];
__device__ float          d_cn[64];
__device__ int            d_done;

// ---------------------------------------------------------------------------
__device__ __forceinline__ uint32_t smem_u32(const void* p) {
    uint32_t a;
    asm("{ .reg .u64 t; cvta.to.shared.u64 t, %1; cvt.u32.u64 %0, t; }" : "=r"(a) : "l"(p));
    return a;
}
#define CP_ASYNC16(sa, gp) \
    asm volatile("cp.async.cg.shared.global [%0], [%1], 16;" :: "r"(sa), "l"(gp))
#define CP_COMMIT() asm volatile("cp.async.commit_group;" ::: "memory")
#define CP_WAIT0()  asm volatile("cp.async.wait_group 0;" ::: "memory")

// ---------------------------------------------------------------------------
// Prep: one warp per row. Lane = one float4 (4 elems). Warp-reduce norm.
__global__ void k_prep(const float* __restrict__ emb, const void* labraw, int n) {
    __shared__ int s_mode;
    const int t = threadIdx.x, lane = t & 31, w = t >> 5;

    if (w == 0) {   // label dtype probe: odd int32 slots of first 32 elems
        const int* lr = (const int*)labraw;
        int v = (lane < n) ? lr[2 * lane + 1] : 0;
        unsigned nz = __ballot_sync(0xFFFFFFFFu, v != 0);
        if (lane == 0) s_mode = (nz == 0);   // all zero => int64 labels
    }
    if (blockIdx.x == 0) {
        if (t < 64) { d_cw[t] = 0.0f; d_cn[t] = 0.0f; }
        if (t == 0) { d_pos = 0.0; d_done = 0; }
    }
    __syncthreads();

    const int row = blockIdx.x * 8 + w;
    if (row >= n) return;

    float4 v = ((const float4*)(emb + (size_t)row * DIM))[lane];
    float s = v.x * v.x + v.y * v.y + v.z * v.z + v.w * v.w;
    #pragma unroll
    for (int o = 16; o > 0; o >>= 1) s += __shfl_down_sync(0xFFFFFFFFu, s, o);

    // bf16 convert: 4 elems -> 8 bytes
    __nv_bfloat162 p0 = __floats2bfloat162_rn(v.x, v.y);
    __nv_bfloat162 p1 = __floats2bfloat162_rn(v.z, v.w);
    *(uint2*)(d_ebf + (size_t)row * DIM + lane * 4) =
        make_uint2(*(uint32_t*)&p0, *(uint32_t*)&p1);

    if (lane == 0) {
        d_sq[row] = s;
        d_lab[row] = s_mode ? ((const int2*)labraw)[row].x : ((const int*)labraw)[row];
    }
}

// ---------------------------------------------------------------------------
__device__ __forceinline__ void mma_bf16(float* d, const uint32_t* a, const uint32_t* b) {
    asm volatile(
        "mma.sync.aligned.m16n8k16.row.col.f32.bf16.bf16.f32 "
        "{%0,%1,%2,%3}, {%4,%5,%6,%7}, {%8,%9}, {%0,%1,%2,%3};"
        : "+f"(d[0]), "+f"(d[1]), "+f"(d[2]), "+f"(d[3])
        : "r"(a[0]), "r"(a[1]), "r"(a[2]), "r"(a[3]), "r"(b[0]), "r"(b[1]));
}
__device__ __forceinline__ void ldmx4(uint32_t* r, uint32_t addr) {
    asm volatile("ldmatrix.sync.aligned.m8n8.x4.shared.b16 {%0,%1,%2,%3}, [%4];"
        : "=r"(r[0]), "=r"(r[1]), "=r"(r[2]), "=r"(r[3]) : "r"(addr));
}

// smem layout (dynamic)
#define SM_RED 0                   /* 8 floats (per-warp partials) */
#define SM_SQI 1024
#define SM_SQJ 1536
#define SM_LI  2048
#define SM_LJ  2560
#define SM_A   3072                /* 128 x LDT bf16 = 34816 B */
#define SM_B   (SM_A + BM * LDT * 2)
#define SM_TOTAL (SM_B + BM * LDT * 2)

__global__ __launch_bounds__(256, 2) void k_main(int n, float* out, int out_size) {
    extern __shared__ char smem[];
    __nv_bfloat16* As = (__nv_bfloat16*)(smem + SM_A);
    __nv_bfloat16* Bs = (__nv_bfloat16*)(smem + SM_B);
    float* sqi_s = (float*)(smem + SM_SQI);
    float* sqj_s = (float*)(smem + SM_SQJ);
    int*   li_s  = (int*)(smem + SM_LI);
    int*   lj_s  = (int*)(smem + SM_LJ);

    const int t = threadIdx.x, w = t >> 5, lane = t & 31;
    const int warp_m = w & 1;          // 2 row groups of 64
    const int warp_n = w >> 1;         // 4 col groups of 32

    // triangular decode: bid -> (ti, tj), ti <= tj
    const int NT = n / BM;
    int bid = blockIdx.x;
    float fN = (float)NT;
    float disc = (2.0f * fN + 1.0f) * (2.0f * fN + 1.0f) - 8.0f * (float)bid;
    int ti = (int)(((2.0f * fN + 1.0f) - sqrtf(disc)) * 0.5f);
    while (ti > 0 && bid < ti * NT - (ti * (ti - 1)) / 2) ti--;
    while (bid >= (ti + 1) * NT - ((ti + 1) * ti) / 2) ti++;
    int tj = ti + (bid - (ti * NT - (ti * (ti - 1)) / 2));
    const int rowBase = ti * BM, colBase = tj * BM;

    // ---- async-load whole-K tiles into padded smem (+ stage sq/lab) ----
    {
        const uint4* gA = (const uint4*)(d_ebf + (size_t)rowBase * DIM);
        const uint4* gB = (const uint4*)(d_ebf + (size_t)colBase * DIM);
        const uint32_t sA = smem_u32(As), sB = smem_u32(Bs);
        #pragma unroll
        for (int i = 0; i < 8; i++) {
            int idx = t + i * 256;                 // 0..2047
            int row = idx >> 4, c8 = idx & 15;
            uint32_t so = (uint32_t)(row * LDT + c8 * 8) * 2;   // bytes; 16B aligned
            CP_ASYNC16(sA + so, gA + row * 16 + c8);
            CP_ASYNC16(sB + so, gB + row * 16 + c8);
        }
        CP_COMMIT();
        if (t < 128) {
            sqi_s[t] = d_sq[rowBase + t];  li_s[t] = d_lab[rowBase + t];
            sqj_s[t] = d_sq[colBase + t];  lj_s[t] = d_lab[colBase + t];
        }
        CP_WAIT0();
    }
    __syncthreads();

    // ---- MMA: warp tile 64x32, m16n8k16, 8 K-steps, ldmatrix loads ----
    float acc[4][4][4];
    #pragma unroll
    for (int mt = 0; mt < 4; mt++)
        #pragma unroll
        for (int nt = 0; nt < 4; nt++)
            #pragma unroll
            for (int q = 0; q < 4; q++) acc[mt][nt][q] = 0.0f;

    const uint32_t sbA = smem_u32(As), sbB = smem_u32(Bs);
    // A x4: lanes 0-15 -> rows 0-15 @k, lanes 16-31 -> rows 0-15 @k+8
    const int rowA  = (lane & 15);
    const int kparA = (lane >> 4) * 8;
    uint32_t adA[4];
    #pragma unroll
    for (int mt = 0; mt < 4; mt++)
        adA[mt] = sbA + ((warp_m * 64 + mt * 16 + rowA) * LDT + kparA) * 2;
    // B x4: groups (n0-7,k) (n0-7,k+8) (n8-15,k) (n8-15,k+8)
    const int rowB  = ((lane >> 4) * 8) + (lane & 7);
    const int kparB = ((lane >> 3) & 1) * 8;
    uint32_t adB[2];
    #pragma unroll
    for (int p = 0; p < 2; p++)
        adB[p] = sbB + ((warp_n * 32 + p * 16 + rowB) * LDT + kparB) * 2;

    #pragma unroll
    for (int ks = 0; ks < 8; ks++) {
        uint32_t a[4][4], b[2][4];
        #pragma unroll
        for (int mt = 0; mt < 4; mt++) { ldmx4(a[mt], adA[mt]); adA[mt] += 32; }
        #pragma unroll
        for (int p = 0; p < 2; p++)    { ldmx4(b[p],  adB[p]);  adB[p]  += 32; }
        #pragma unroll
        for (int mt = 0; mt < 4; mt++) {
            mma_bf16(acc[mt][0], a[mt], &b[0][0]);
            mma_bf16(acc[mt][1], a[mt], &b[0][2]);
            mma_bf16(acc[mt][2], a[mt], &b[1][0]);
            mma_bf16(acc[mt][3], a[mt], &b[1][2]);
        }
    }

    // ---- fused epilogue ----
    float rsq[8], csq[8];
    int   rlb[8], clb[8];
    #pragma unroll
    for (int u = 0; u < 8; u++) {
        int il = warp_m * 64 + (u >> 1) * 16 + (lane >> 2) + (u & 1) * 8;
        rsq[u] = sqi_s[il]; rlb[u] = li_s[il];
        int jl = warp_n * 32 + (u >> 1) * 8 + (lane & 3) * 2 + (u & 1);
        csq[u] = sqj_s[jl]; clb[u] = lj_s[jl];
    }

    const bool diag = (ti == tj);
    float pos0 = 0.0f, pos1 = 0.0f;

    #pragma unroll
    for (int mt = 0; mt < 4; mt++) {
        #pragma unroll
        for (int nt = 0; nt < 4; nt++) {
            #pragma unroll
            for (int q = 0; q < 4; q++) {
                int ui = mt * 2 + (q >> 1);
                int uj = nt * 2 + (q & 1);
                if (diag) {
                    int gi = rowBase + warp_m * 64 + mt * 16 + (lane >> 2) + (q >> 1) * 8;
                    int gj = colBase + warp_n * 32 + nt * 8 + (lane & 3) * 2 + (q & 1);
                    if (gj <= gi) continue;
                }
                float dist = fmaf(-2.0f, acc[mt][nt][q], rsq[ui] + csq[uj]);
                int li = rlb[ui], lj = clb[uj];
                if (li == lj) {
                    if (dist > APM) { if (q & 1) pos1 += dist - APM; else pos0 += dist - APM; }
                } else if (dist < ALPHAC) {          // statistically cold
                    float gap = ALPHAC - dist;
                    float ww = expf(TC * gap);
                    atomicAdd(&d_cw[li], ww); atomicAdd(&d_cn[li], gap * ww);
                    atomicAdd(&d_cw[lj], ww); atomicAdd(&d_cn[lj], gap * ww);
                }
            }
        }
    }
    float pos = (pos0 + pos1) * 2.0f;   // each unordered pair appears twice

    // warp shuffle reduce -> 8 partials -> warp 0 -> one double atomic
    #pragma unroll
    for (int o = 16; o > 0; o >>= 1) pos += __shfl_down_sync(0xFFFFFFFFu, pos, o);
    float* red = (float*)(smem + SM_RED);
    if (lane == 0) red[w] = pos;
    __syncthreads();
    if (t == 0) {
        float s = red[0] + red[1] + red[2] + red[3]
                + red[4] + red[5] + red[6] + red[7];
        atomicAdd(&d_pos, (double)s);
        __threadfence();
        int ticket = atomicAdd(&d_done, 1);
        if (ticket == (int)gridDim.x - 1) {
            __threadfence();
            volatile float* vw = d_cw;
            volatile float* vn = d_cn;
            volatile double* vp = &d_pos;
            double neg = 0.0;
            #pragma unroll 8
            for (int c = 0; c < 64; c++) {
                float wv = vw[c];
                if (wv > 0.0f) neg += (double)(vn[c] / wv);
            }
            out[0] = (float)(*vp + neg);
            if (out_size > 1) out[1] = (float)n;
        }
    }
}

// ---------------------------------------------------------------------------
extern "C" void kernel_launch(void* const* d_in, const int* in_sizes, int n_in,
                              void* d_out, int out_size) {
    const float* emb = (const float*)d_in[0];
    const void*  lab = d_in[1];
    int n = in_sizes[1];               // 8192
    float* out = (float*)d_out;

    cudaFuncSetAttribute(k_main, cudaFuncAttributeMaxDynamicSharedMemorySize, SM_TOTAL);

    k_prep<<<(n + 7) / 8, 256>>>(emb, lab, n);     // one warp per row

    int nt = n / BM;
    int nblocks = nt * (nt + 1) / 2;
    k_main<<<nblocks, 256, SM_TOTAL>>>(n, out, out_size);
}

// round 14
// speedup vs baseline: 1.6399x; 1.1135x over previous
#include <cuda_runtime.h>
#include <cuda_bf16.h>
#include <cstdint>

// RankedListLoss, round 12: persistent CTAs, cross-tile prefetch overlap,
// mma.sync bf16 + ldmatrix, single end-of-kernel reduction.
//
// dist(i,j) = sq_i + sq_j - 2*dot(e_i,e_j)   (sq fp32, dot bf16 tensor cores)
// pos: sum {same class, i!=j, dist > 0.8} (dist - 0.8)
// neg: per class, softmax-weighted gap over cross-class pairs with dist < 1.2

#define NMAX 8192
#define DIM 128
#define BM 128
#define LDT 136            /* padded smem row stride (bf16); 272B row pitch */
#define APM 0.8f
#define ALPHAC 1.2f
#define TC 10.0f
#define PERS_GRID 304      /* ~2 CTAs per SM on 148-152 SM parts */

__device__ float          d_sq[NMAX];
__device__ int            d_lab[NMAX];
__device__ __nv_bfloat16  d_ebf[NMAX * DIM];
__device__ double         d_pos;
__device__ float          d_cw[64];
__device__ float          d_cn[64];
__device__ int            d_done;

// ---------------------------------------------------------------------------
__device__ __forceinline__ uint32_t smem_u32(const void* p) {
    uint32_t a;
    asm("{ .reg .u64 t; cvta.to.shared.u64 t, %1; cvt.u32.u64 %0, t; }" : "=r"(a) : "l"(p));
    return a;
}
#define CP_ASYNC16(sa, gp) \
    asm volatile("cp.async.cg.shared.global [%0], [%1], 16;" :: "r"(sa), "l"(gp))
#define CP_COMMIT() asm volatile("cp.async.commit_group;" ::: "memory")
#define CP_WAIT0()  asm volatile("cp.async.wait_group 0;" ::: "memory")

// ---------------------------------------------------------------------------
// Prep: one warp per row; lane = one float4; warp-reduce norm; bf16 copy.
__global__ void k_prep(const float* __restrict__ emb, const void* labraw, int n) {
    __shared__ int s_mode;
    const int t = threadIdx.x, lane = t & 31, w = t >> 5;

    if (w == 0) {   // label dtype probe: odd int32 slots of first 32 elems
        const int* lr = (const int*)labraw;
        int v = (lane < n) ? lr[2 * lane + 1] : 0;
        unsigned nz = __ballot_sync(0xFFFFFFFFu, v != 0);
        if (lane == 0) s_mode = (nz == 0);   // all zero => int64 labels
    }
    if (blockIdx.x == 0) {
        if (t < 64) { d_cw[t] = 0.0f; d_cn[t] = 0.0f; }
        if (t == 0) { d_pos = 0.0; d_done = 0; }
    }
    __syncthreads();

    const int row = blockIdx.x * 8 + w;
    if (row >= n) return;

    float4 v = ((const float4*)(emb + (size_t)row * DIM))[lane];
    float s = v.x * v.x + v.y * v.y + v.z * v.z + v.w * v.w;
    #pragma unroll
    for (int o = 16; o > 0; o >>= 1) s += __shfl_down_sync(0xFFFFFFFFu, s, o);

    __nv_bfloat162 p0 = __floats2bfloat162_rn(v.x, v.y);
    __nv_bfloat162 p1 = __floats2bfloat162_rn(v.z, v.w);
    *(uint2*)(d_ebf + (size_t)row * DIM + lane * 4) =
        make_uint2(*(uint32_t*)&p0, *(uint32_t*)&p1);

    if (lane == 0) {
        d_sq[row] = s;
        d_lab[row] = s_mode ? ((const int2*)labraw)[row].x : ((const int*)labraw)[row];
    }
}

// ---------------------------------------------------------------------------
__device__ __forceinline__ void mma_bf16(float* d, const uint32_t* a, const uint32_t* b) {
    asm volatile(
        "mma.sync.aligned.m16n8k16.row.col.f32.bf16.bf16.f32 "
        "{%0,%1,%2,%3}, {%4,%5,%6,%7}, {%8,%9}, {%0,%1,%2,%3};"
        : "+f"(d[0]), "+f"(d[1]), "+f"(d[2]), "+f"(d[3])
        : "r"(a[0]), "r"(a[1]), "r"(a[2]), "r"(a[3]), "r"(b[0]), "r"(b[1]));
}
__device__ __forceinline__ void ldmx4(uint32_t* r, uint32_t addr) {
    asm volatile("ldmatrix.sync.aligned.m8n8.x4.shared.b16 {%0,%1,%2,%3}, [%4];"
        : "=r"(r[0]), "=r"(r[1]), "=r"(r[2]), "=r"(r[3]) : "r"(addr));
}

// smem layout (dynamic)
#define SM_RED   0                 /* 8 floats */
#define SM_META  1024              /* 2 bufs x 2048 B: sqi|sqj|li|lj (128 ea) */
#define SM_A     8192              /* 128 x LDT bf16 = 34816 B */
#define SM_B     (SM_A + BM * LDT * 2)
#define SM_TOTAL (SM_B + BM * LDT * 2)

__global__ __launch_bounds__(256, 2) void k_main(int n, float* out, int out_size) {
    extern __shared__ char smem[];
    __nv_bfloat16* As = (__nv_bfloat16*)(smem + SM_A);
    __nv_bfloat16* Bs = (__nv_bfloat16*)(smem + SM_B);

    const int t = threadIdx.x, w = t >> 5, lane = t & 31;
    const int warp_m = w & 1;          // 2 row groups of 64
    const int warp_n = w >> 1;         // 4 col groups of 32
    const int NT = n / BM;
    const int ntiles = NT * (NT + 1) / 2;

    // loop-invariant cp.async source/dst geometry (per thread, 16 chunks)
    const uint32_t sA = smem_u32(As), sB = smem_u32(Bs);
    // loop-invariant ldmatrix addresses
    const int rowA  = (lane & 15);
    const int kparA = (lane >> 4) * 8;
    uint32_t adA0[4];
    #pragma unroll
    for (int mt = 0; mt < 4; mt++)
        adA0[mt] = sA + ((warp_m * 64 + mt * 16 + rowA) * LDT + kparA) * 2;
    const int rowB  = ((lane >> 4) * 8) + (lane & 7);
    const int kparB = ((lane >> 3) & 1) * 8;
    uint32_t adB0[2];
    #pragma unroll
    for (int p = 0; p < 2; p++)
        adB0[p] = sB + ((warp_n * 32 + p * 16 + rowB) * LDT + kparB) * 2;

    // ---- tile prefetch helper (A/B via cp.async, meta via plain st) ----
    auto prefetch = [&](int rowBase, int colBase, int buf) {
        const uint4* gA = (const uint4*)(d_ebf + (size_t)rowBase * DIM);
        const uint4* gB = (const uint4*)(d_ebf + (size_t)colBase * DIM);
        #pragma unroll
        for (int i = 0; i < 8; i++) {
            int idx = t + i * 256;
            int row = idx >> 4, c8 = idx & 15;
            uint32_t so = (uint32_t)(row * LDT + c8 * 8) * 2;
            CP_ASYNC16(sA + so, gA + row * 16 + c8);
            CP_ASYNC16(sB + so, gB + row * 16 + c8);
        }
        CP_COMMIT();
        char* mb = smem + SM_META + buf * 2048;
        if (t < 128) {
            ((float*)mb)[t]         = d_sq[rowBase + t];
            ((float*)(mb + 512))[t] = d_sq[colBase + t];
            ((int*)(mb + 1024))[t]  = d_lab[rowBase + t];
            ((int*)(mb + 1536))[t]  = d_lab[colBase + t];
        }
    };
    auto decode = [&](int bid, int& ti, int& tj) {
        float fN = (float)NT;
        float disc = (2.0f * fN + 1.0f) * (2.0f * fN + 1.0f) - 8.0f * (float)bid;
        ti = (int)(((2.0f * fN + 1.0f) - sqrtf(disc)) * 0.5f);
        while (ti > 0 && bid < ti * NT - (ti * (ti - 1)) / 2) ti--;
        while (bid >= (ti + 1) * NT - ((ti + 1) * ti) / 2) ti++;
        tj = ti + (bid - (ti * NT - (ti * (ti - 1)) / 2));
    };

    // ---- persistent loop ----
    int tile = blockIdx.x;
    int ti = 0, tj = 0;
    if (tile < ntiles) {
        decode(tile, ti, tj);
        prefetch(ti * BM, tj * BM, 0);
        CP_WAIT0();
        __syncthreads();
    }
    float posa = 0.0f;
    int buf = 0;

    while (tile < ntiles) {
        const int cur_ti = ti, cur_tj = tj;
        const int rowBase = cur_ti * BM, colBase = cur_tj * BM;

        // ---- mainloop: warp tile 64x32, 8 K-steps ----
        float acc[4][4][4];
        #pragma unroll
        for (int mt = 0; mt < 4; mt++)
            #pragma unroll
            for (int nt = 0; nt < 4; nt++)
                #pragma unroll
                for (int q = 0; q < 4; q++) acc[mt][nt][q] = 0.0f;

        uint32_t adA[4] = {adA0[0], adA0[1], adA0[2], adA0[3]};
        uint32_t adB[2] = {adB0[0], adB0[1]};
        #pragma unroll
        for (int ks = 0; ks < 8; ks++) {
            uint32_t a[4][4], b[2][4];
            #pragma unroll
            for (int mt = 0; mt < 4; mt++) { ldmx4(a[mt], adA[mt]); adA[mt] += 32; }
            #pragma unroll
            for (int p = 0; p < 2; p++)    { ldmx4(b[p],  adB[p]);  adB[p]  += 32; }
            #pragma unroll
            for (int mt = 0; mt < 4; mt++) {
                mma_bf16(acc[mt][0], a[mt], &b[0][0]);
                mma_bf16(acc[mt][1], a[mt], &b[0][2]);
                mma_bf16(acc[mt][2], a[mt], &b[1][0]);
                mma_bf16(acc[mt][3], a[mt], &b[1][2]);
            }
        }
        __syncthreads();                 // all warps done reading As/Bs

        // ---- prefetch next tile (overlaps with epilogue below) ----
        int next = tile + gridDim.x;
        if (next < ntiles) {
            decode(next, ti, tj);
            prefetch(ti * BM, tj * BM, buf ^ 1);
        }

        // ---- epilogue on current tile (meta[buf]) ----
        {
            char* mb = smem + SM_META + buf * 2048;
            float* sqi_s = (float*)mb;
            float* sqj_s = (float*)(mb + 512);
            int*   li_s  = (int*)(mb + 1024);
            int*   lj_s  = (int*)(mb + 1536);

            float rsq[8], csq[8];
            int   rlb[8], clb[8];
            #pragma unroll
            for (int u = 0; u < 8; u++) {
                int il = warp_m * 64 + (u >> 1) * 16 + (lane >> 2) + (u & 1) * 8;
                rsq[u] = sqi_s[il]; rlb[u] = li_s[il];
                int jl = warp_n * 32 + (u >> 1) * 8 + (lane & 3) * 2 + (u & 1);
                csq[u] = sqj_s[jl]; clb[u] = lj_s[jl];
            }

            const bool diag = (cur_ti == cur_tj);
            #pragma unroll
            for (int mt = 0; mt < 4; mt++) {
                #pragma unroll
                for (int nt = 0; nt < 4; nt++) {
                    #pragma unroll
                    for (int q = 0; q < 4; q++) {
                        int ui = mt * 2 + (q >> 1);
                        int uj = nt * 2 + (q & 1);
                        if (diag) {
                            int gi = rowBase + warp_m * 64 + mt * 16 + (lane >> 2) + (q >> 1) * 8;
                            int gj = colBase + warp_n * 32 + nt * 8 + (lane & 3) * 2 + (q & 1);
                            if (gj <= gi) continue;
                        }
                        float dist = fmaf(-2.0f, acc[mt][nt][q], rsq[ui] + csq[uj]);
                        int li = rlb[ui], lj = clb[uj];
                        if (li == lj) {
                            if (dist > APM) posa += dist - APM;
                        } else if (dist < ALPHAC) {     // statistically cold
                            float gap = ALPHAC - dist;
                            float ww = expf(TC * gap);
                            atomicAdd(&d_cw[li], ww); atomicAdd(&d_cn[li], gap * ww);
                            atomicAdd(&d_cw[lj], ww); atomicAdd(&d_cn[lj], gap * ww);
                        }
                    }
                }
            }
        }

        buf ^= 1;
        tile = next;
        if (tile < ntiles) {
            CP_WAIT0();
            __syncthreads();             // next tile data + meta visible
        }
    }

    // ---- single end-of-kernel reduction ----
    float pos = posa * 2.0f;             // each unordered pair counted twice
    #pragma unroll
    for (int o = 16; o > 0; o >>= 1) pos += __shfl_down_sync(0xFFFFFFFFu, pos, o);
    float* red = (float*)(smem + SM_RED);
    if (lane == 0) red[w] = pos;
    __syncthreads();
    if (t == 0) {
        float s = red[0] + red[1] + red[2] + red[3]
                + red[4] + red[5] + red[6] + red[7];
        atomicAdd(&d_pos, (double)s);
        __threadfence();
        int ticket = atomicAdd(&d_done, 1);
        if (ticket == (int)gridDim.x - 1) {
            __threadfence();
            volatile float* vw = d_cw;
            volatile float* vn = d_cn;
            volatile double* vp = &d_pos;
            double neg = 0.0;
            #pragma unroll 8
            for (int c = 0; c < 64; c++) {
                float wv = vw[c];
                if (wv > 0.0f) neg += (double)(vn[c] / wv);
            }
            out[0] = (float)(*vp + neg);
            if (out_size > 1) out[1] = (float)n;
        }
    }
}

// ---------------------------------------------------------------------------
extern "C" void kernel_launch(void* const* d_in, const int* in_sizes, int n_in,
                              void* d_out, int out_size) {
    const float* emb = (const float*)d_in[0];
    const void*  lab = d_in[1];
    int n = in_sizes[1];               // 8192
    float* out = (float*)d_out;

    cudaFuncSetAttribute(k_main, cudaFuncAttributeMaxDynamicSharedMemorySize, SM_TOTAL);

    k_prep<<<(n + 7) / 8, 256>>>(emb, lab, n);     // one warp per row

    int nt = n / BM;
    int nblocks = nt * (nt + 1) / 2;
    int grid = nblocks < PERS_GRID ? nblocks : PERS_GRID;
    k_main<<<grid, 256, SM_TOTAL>>>(n, out, out_size);
}